// round 13
// baseline (speedup 1.0000x reference)
#include <cuda_runtime.h>
#include <cuda_fp16.h>
#include <cstdint>

// ============================================================================
// EdgeUpdate, round 12: R11 + ef-conversion deferred into chunks 0/1
// (overlaps its LDG latency with GEMM1 compute) + vectorized prep_node.
//  - 256 threads/CTA, 8 warps, warp tile 64 edges x 32 channels, 2 CTAs/SM
//  - node gather: cp.async from fp16 g_ni16; ef: LDG fp32 -> cvt -> STS fp16
//    executed inside chunks 0-1 (consumed from chunk 2 onward)
//  - residual: exact fp32 edge_features re-read from gmem (L2-hot) in epilogue
//  - fragments via ldmatrix.m8n8.x4.b16; mma.m16n8k16.f32.f16
// ============================================================================

#define THREADS   256
#define TILE      128
#define HD        128
#define LN_EPS    1e-5f
#define S_A       264     // A16 row stride (halfs)
#define S_W       72      // W chunk row stride (halfs)

// smem byte offsets
#define O_A16    0
#define O_W16    67584                    // 128*264*2
#define O_PART   (O_W16 + 36864)          // 104448 (float2[128][4]) / idxs alias
#define O_STATS  (O_PART + 4096)          // 108544 (float2[128])
#define O_B1     (O_STATS + 1024)         // 109568
#define O_B2     (O_B1 + 512)
#define O_GM     (O_B2 + 512)
#define O_BT     (O_GM + 512)
#define SMEM_BYTES (O_BT + 512)           // 111616 (109 KB) -> 2 CTAs/SM

__device__ __half g_ni16[50000 * 64];     // node_inv in fp16
__device__ __half g_Wt16[49152];          // W1^T [128][256] ++ W2^T [128][128]

__device__ __forceinline__ void mma16(float* d, const uint32_t* a,
                                      uint32_t b0, uint32_t b1) {
    asm volatile(
        "mma.sync.aligned.m16n8k16.row.col.f32.f16.f16.f32 "
        "{%0,%1,%2,%3}, {%4,%5,%6,%7}, {%8,%9}, {%0,%1,%2,%3};"
        : "+f"(d[0]), "+f"(d[1]), "+f"(d[2]), "+f"(d[3])
        : "r"(a[0]), "r"(a[1]), "r"(a[2]), "r"(a[3]), "r"(b0), "r"(b1));
}

#define LDSM4(r, addr)                                                          \
    asm volatile("ldmatrix.sync.aligned.m8n8.x4.shared.b16 {%0,%1,%2,%3}, [%4];"\
        : "=r"((r)[0]), "=r"((r)[1]), "=r"((r)[2]), "=r"((r)[3]) : "r"(addr))

__device__ __forceinline__ uint32_t smem_u32(const void* p) {
    uint32_t a;
    asm("{ .reg .u64 t; cvta.to.shared.u64 t, %1; cvt.u32.u64 %0, t; }" : "=r"(a) : "l"(p));
    return a;
}
__device__ __forceinline__ void cp16(uint32_t dst, const void* src) {
    asm volatile("cp.async.cg.shared.global [%0], [%1], 16;" :: "r"(dst), "l"(src));
}
#define CP_COMMIT() asm volatile("cp.async.commit_group;" ::: "memory")
#define CP_WAIT(N)  asm volatile("cp.async.wait_group %0;" :: "n"(N) : "memory")

__global__ void prep_node(const float* __restrict__ node_inv, int n8) {
    int i = blockIdx.x * blockDim.x + threadIdx.x;   // one per 8 floats
    if (i < n8) {
        float4 v0 = ((const float4*)node_inv)[2 * i];
        float4 v1 = ((const float4*)node_inv)[2 * i + 1];
        __half2 h[4] = { __floats2half2_rn(v0.x, v0.y), __floats2half2_rn(v0.z, v0.w),
                         __floats2half2_rn(v1.x, v1.y), __floats2half2_rn(v1.z, v1.w) };
        ((uint4*)g_ni16)[i] = *(uint4*)h;
    }
}
__global__ void prep_w(const float* __restrict__ W1, const float* __restrict__ W2) {
    int i = blockIdx.x * blockDim.x + threadIdx.x;      // i = c*K + k
    if (i < 32768) {
        int c = i >> 8, k = i & 255;
        g_Wt16[i] = __float2half_rn(W1[k * HD + c]);
    } else if (i < 49152) {
        int j = i - 32768;
        int c = j >> 7, k = j & 127;
        g_Wt16[i] = __float2half_rn(W2[k * HD + c]);
    }
}

__global__ __launch_bounds__(THREADS, 2)
void edge_update_mma(const float* __restrict__ edge_features,
                     const void*  __restrict__ edge_src,
                     const void*  __restrict__ edge_dst,
                     const float* __restrict__ b1,
                     const float* __restrict__ b2,
                     const float* __restrict__ gamma,
                     const float* __restrict__ beta,
                     float* __restrict__ out,
                     int n_edges)
{
    extern __shared__ char smc[];
    __half* A16   = (__half*)(smc + O_A16);
    float2* part  = (float2*)(smc + O_PART);
    float2* stats = (float2*)(smc + O_STATS);
    int*    idxs  = (int*)(smc + O_PART);     // alias: gather phase only
    float*  cb1   = (float*)(smc + O_B1);
    float*  cb2   = (float*)(smc + O_B2);
    float*  cgm   = (float*)(smc + O_GM);
    float*  cbt   = (float*)(smc + O_BT);

    const uint32_t a16b = smem_u32(A16);
    const uint32_t wbb  = smem_u32(smc + O_W16);

    const int tid  = threadIdx.x;
    const int wid  = tid >> 5;
    const int lane = tid & 31;
    const int g    = lane >> 2;
    const int t    = lane & 3;
    const int mrow = (wid >> 2) * 64;     // 2 M-halves
    const int ncol = (wid & 3) * 32;      // 4 N-quarters
    const int wN   = wid & 3;

    const int e_base = blockIdx.x * TILE;

    // index dtype sniff (int64 buffers have zero high words)
    const int* s32c = (const int*)edge_src;
    const bool idx64 = ((s32c[1] | s32c[3] | s32c[5] | s32c[7]) == 0);

    // ---- W chunk staging: 128 rows x 64 halfs = 1024 x 16B ----
    auto stage = [&](int ch) {
        const __half* src;
        int kA, kstr;
        if (ch < 4) { src = g_Wt16;         kA = ch * 64;       kstr = 256; }
        else        { src = g_Wt16 + 32768; kA = (ch - 4) * 64; kstr = 128; }
        uint32_t dstb = wbb + (uint32_t)((ch & 1) * 128 * S_W) * 2u;
        #pragma unroll
        for (int i = 0; i < 4; ++i) {
            int idx = tid + i * THREADS;   // 0..1023
            int c   = idx >> 3;            // channel row
            int q   = idx & 7;             // 8-half quad
            cp16(dstb + (uint32_t)(c * S_W + q * 8) * 2u,
                 src + c * kstr + kA + q * 8);
        }
        CP_COMMIT();
    };
    stage(0);                               // group: s0

    if (tid < 128) {
        cb1[tid] = b1[tid];
        cb2[tid] = b2[tid];
        cgm[tid] = gamma[tid];
        cbt[tid] = beta[tid];
    }

    // ---- stage edge indices ----
    {
        int e  = tid & 127;
        int eg = e_base + e;
        if (eg >= n_edges) eg = n_edges - 1;
        const int* p = (const int*)((tid < 128) ? edge_src : edge_dst);
        idxs[tid] = idx64 ? p[2 * eg] : p[eg];
    }
    __syncthreads();

    // ---- gather gA: node halfs -> A16 cols 0..127 (16B = 8 halfs) ----
    #pragma unroll
    for (int it = 0; it < 8; ++it) {
        int q = tid + it * THREADS;          // 0..2047
        int e = q >> 4;
        int j = q & 15;                      // 8-half quad: 0-7 src, 8-15 dst
        int node = idxs[(j < 8 ? 0 : 128) + e];
        cp16(a16b + (uint32_t)(e * S_A + j * 8) * 2u,
             g_ni16 + (long long)node * 64 + (j & 7) * 8);
    }
    CP_COMMIT();                             // group: gA

    stage(1);                                // group: s1

    // per-lane static ldmatrix byte offsets
    const uint32_t a_off = (uint32_t)((mrow + (lane & 15)) * S_A + ((lane >> 4) & 1) * 8) * 2u;
    const uint32_t b_off = (uint32_t)((ncol + (lane & 15)) * S_W + ((lane >> 4) & 1) * 8) * 2u;

    float acc[4][4][4];
    #pragma unroll
    for (int mb = 0; mb < 4; ++mb)
        #pragma unroll
        for (int nb = 0; nb < 4; ++nb)
            #pragma unroll
            for (int r = 0; r < 4; ++r) acc[mb][nb][r] = 0.f;

    const int eg_max = n_edges - 1;

    // Wait ledger (stage AFTER sync):
    //  ch0: pending {s0,gA,s1} -> wait(1) drains s0,gA (needs s0,gA)
    //  ch1: pending {s1,s2} -> wait(1) drains s1
    //  ch2-4: wait(1);  ch5: wait(0)
    // ef conversion (A cols 128..255, consumed from ch2) is executed inside
    // ch0/ch1 after their ks-loops; ch2-top __syncthreads orders the STS.
    #pragma unroll 1
    for (int ch = 0; ch < 6; ++ch) {
        if (ch < 5)  CP_WAIT(1);
        else         CP_WAIT(0);
        __syncthreads();
        if (ch >= 1 && ch < 5) stage(ch + 1);

        const uint32_t wchunk = wbb + (uint32_t)((ch & 1) * 128 * S_W) * 2u;
        const int kA = (ch < 4) ? ch * 64 : (ch - 4) * 64;   // halfs
        const uint32_t abase = a16b + a_off + (uint32_t)kA * 2u;
        const uint32_t bbase = wchunk + b_off;

        #pragma unroll
        for (int ks = 0; ks < 4; ++ks) {
            const uint32_t kb = (uint32_t)(ks * 16) * 2u;
            uint32_t a[4][4], b[2][4];
            LDSM4(a[0], abase + kb);
            LDSM4(a[1], abase + (uint32_t)(16 * S_A) * 2u + kb);
            LDSM4(a[2], abase + (uint32_t)(32 * S_A) * 2u + kb);
            LDSM4(a[3], abase + (uint32_t)(48 * S_A) * 2u + kb);
            LDSM4(b[0], bbase + kb);
            LDSM4(b[1], bbase + (uint32_t)(16 * S_W) * 2u + kb);
            #pragma unroll
            for (int mb = 0; mb < 4; ++mb) {
                mma16(acc[mb][0], a[mb], b[0][0], b[0][2]);
                mma16(acc[mb][1], a[mb], b[0][1], b[0][3]);
                mma16(acc[mb][2], a[mb], b[1][0], b[1][2]);
                mma16(acc[mb][3], a[mb], b[1][1], b[1][3]);
            }
        }

        if (ch < 2) {
            // ef: LDG fp32 -> cvt -> STS fp16 into A16 cols 128..255.
            // Half per chunk; overlaps GEMM1 compute. Consumed from ch2.
            #pragma unroll
            for (int it = 0; it < 8; ++it) {
                int q = tid + (ch * 8 + it) * THREADS;   // 0..4095
                int e = q >> 5;
                int j = q & 31;                          // 4-float quad
                int eg = e_base + e; if (eg > eg_max) eg = eg_max;
                float4 v = *(const float4*)(edge_features + (long long)eg * HD + j * 4);
                *(__half2*)&A16[e * S_A + 128 + j * 4]     = __floats2half2_rn(v.x, v.y);
                *(__half2*)&A16[e * S_A + 128 + j * 4 + 2] = __floats2half2_rn(v.z, v.w);
            }
        }

        if (ch == 3) {
            // h = relu(D1 + b1) -> fp16 into A16 cols 0..127
            // (cols 0..127 last read at ch1; ch4-top sync orders vs GEMM2 reads)
            #pragma unroll
            for (int mb = 0; mb < 4; ++mb) {
                const int r0 = mrow + mb * 16 + g;
                #pragma unroll
                for (int nb = 0; nb < 4; ++nb) {
                    const int c0 = ncol + nb * 8 + 2 * t;
                    const float bb0 = cb1[c0], bb1 = cb1[c0 + 1];
                    *(__half2*)&A16[r0 * S_A + c0] =
                        __floats2half2_rn(fmaxf(acc[mb][nb][0] + bb0, 0.f),
                                          fmaxf(acc[mb][nb][1] + bb1, 0.f));
                    *(__half2*)&A16[(r0 + 8) * S_A + c0] =
                        __floats2half2_rn(fmaxf(acc[mb][nb][2] + bb0, 0.f),
                                          fmaxf(acc[mb][nb][3] + bb1, 0.f));
                }
            }
            #pragma unroll
            for (int mb = 0; mb < 4; ++mb)
                #pragma unroll
                for (int nb = 0; nb < 4; ++nb)
                    #pragma unroll
                    for (int r = 0; r < 4; ++r) acc[mb][nb][r] = 0.f;
        }
    }

    // ---- epilogue: u = D2 + b2; LayerNorm; residual; store ----
    #pragma unroll
    for (int mb = 0; mb < 4; ++mb)
        #pragma unroll
        for (int nb = 0; nb < 4; ++nb) {
            const int c0 = ncol + nb * 8 + 2 * t;
            acc[mb][nb][0] += cb2[c0];
            acc[mb][nb][1] += cb2[c0 + 1];
            acc[mb][nb][2] += cb2[c0];
            acc[mb][nb][3] += cb2[c0 + 1];
        }

    __syncthreads();   // idxs alias dead; part safe to write

    #pragma unroll
    for (int mb = 0; mb < 4; ++mb) {
        float s0 = 0.f, ss0 = 0.f, s1 = 0.f, ss1 = 0.f;
        #pragma unroll
        for (int nb = 0; nb < 4; ++nb) {
            float u0 = acc[mb][nb][0], u1 = acc[mb][nb][1];
            float u2 = acc[mb][nb][2], u3 = acc[mb][nb][3];
            s0 += u0 + u1;  ss0 += u0 * u0 + u1 * u1;
            s1 += u2 + u3;  ss1 += u2 * u2 + u3 * u3;
        }
        #pragma unroll
        for (int m = 1; m < 4; m <<= 1) {
            s0  += __shfl_xor_sync(0xffffffffu, s0,  m);
            ss0 += __shfl_xor_sync(0xffffffffu, ss0, m);
            s1  += __shfl_xor_sync(0xffffffffu, s1,  m);
            ss1 += __shfl_xor_sync(0xffffffffu, ss1, m);
        }
        if (t == 0) {
            int e0 = mrow + mb * 16 + g;
            part[e0 * 4 + wN]       = make_float2(s0, ss0);
            part[(e0 + 8) * 4 + wN] = make_float2(s1, ss1);
        }
    }
    __syncthreads();

    if (tid < TILE) {
        float s = 0.f, ss = 0.f;
        #pragma unroll
        for (int q = 0; q < 4; ++q) {
            float2 p = part[tid * 4 + q];
            s += p.x; ss += p.y;
        }
        float mu  = s * (1.f / 128.f);
        float var = ss * (1.f / 128.f) - mu * mu;
        stats[tid] = make_float2(mu, rsqrtf(var + LN_EPS));
    }
    __syncthreads();

    #pragma unroll
    for (int mb = 0; mb < 4; ++mb) {
        const int r0 = mrow + mb * 16 + g;
        const float2 st0 = stats[r0];
        const float2 st1 = stats[r0 + 8];
        const int eg0 = e_base + r0;
        const int eg1 = eg0 + 8;
        #pragma unroll
        for (int nb = 0; nb < 4; ++nb) {
            const int c0 = ncol + nb * 8 + 2 * t;
            const float gm0 = cgm[c0], gm1 = cgm[c0 + 1];
            const float bt0 = cbt[c0], bt1 = cbt[c0 + 1];
            if (eg0 < n_edges) {
                float2 ef = *(const float2*)(edge_features + (long long)eg0 * HD + c0);
                float2 o;
                o.x = ef.x + (acc[mb][nb][0] - st0.x) * st0.y * gm0 + bt0;
                o.y = ef.y + (acc[mb][nb][1] - st0.x) * st0.y * gm1 + bt1;
                *(float2*)&out[(long long)eg0 * HD + c0] = o;
            }
            if (eg1 < n_edges) {
                float2 ef = *(const float2*)(edge_features + (long long)eg1 * HD + c0);
                float2 o;
                o.x = ef.x + (acc[mb][nb][2] - st1.x) * st1.y * gm0 + bt0;
                o.y = ef.y + (acc[mb][nb][3] - st1.x) * st1.y * gm1 + bt1;
                *(float2*)&out[(long long)eg1 * HD + c0] = o;
            }
        }
    }
}

extern "C" void kernel_launch(void* const* d_in, const int* in_sizes, int n_in,
                              void* d_out, int out_size)
{
    const float* node_inv      = (const float*)d_in[0];
    const float* edge_features = (const float*)d_in[1];
    const void*  edge_src      = d_in[2];
    const void*  edge_dst      = d_in[3];
    const float* W1            = (const float*)d_in[4];
    const float* b1            = (const float*)d_in[5];
    const float* W2            = (const float*)d_in[6];
    const float* b2            = (const float*)d_in[7];
    const float* gamma         = (const float*)d_in[8];
    const float* beta          = (const float*)d_in[9];
    float* out = (float*)d_out;

    int n_edges = in_sizes[1] / HD;
    int n_node_elems = in_sizes[0];
    if (n_node_elems > 50000 * 64) n_node_elems = 50000 * 64;
    int n8 = n_node_elems / 8;

    prep_node<<<(n8 + 255) / 256, 256>>>(node_inv, n8);
    prep_w<<<(49152 + 255) / 256, 256>>>(W1, W2);

    cudaFuncSetAttribute(edge_update_mma,
                         cudaFuncAttributeMaxDynamicSharedMemorySize, SMEM_BYTES);

    int grid = (n_edges + TILE - 1) / TILE;
    edge_update_mma<<<grid, THREADS, SMEM_BYTES>>>(
        edge_features, edge_src, edge_dst,
        b1, b2, gamma, beta, out, n_edges);
}

// round 15
// speedup vs baseline: 1.0329x; 1.0329x over previous
#include <cuda_runtime.h>
#include <cuda_fp16.h>
#include <cstdint>

// ============================================================================
// EdgeUpdate, round 14: R13 with the ef-batch indexing bug fixed
// (e = q>>5, j = q&31 — 32 float4-quads per edge, as in R11).
//  - 256 threads/CTA, 8 warps, warp tile 64 edges x 32 channels, 2 CTAs/SM
//  - node gather: cp.async from fp16 g_ni16
//  - ef: LDG fp32 in 2 register batches issued AROUND the gather/stage issue
//    (latency hidden), then cvt -> STS fp16 into A16 cols 128..255
//  - residual: exact fp32 edge_features re-read from gmem (L2-hot) in epilogue
//  - fragments via ldmatrix.m8n8.x4.b16; mma.m16n8k16.f32.f16
// ============================================================================

#define THREADS   256
#define TILE      128
#define HD        128
#define LN_EPS    1e-5f
#define S_A       264     // A16 row stride (halfs)
#define S_W       72      // W chunk row stride (halfs)

// smem byte offsets
#define O_A16    0
#define O_W16    67584                    // 128*264*2
#define O_PART   (O_W16 + 36864)          // 104448 (float2[128][4]) / idxs alias
#define O_STATS  (O_PART + 4096)          // 108544 (float2[128])
#define O_B1     (O_STATS + 1024)         // 109568
#define O_B2     (O_B1 + 512)
#define O_GM     (O_B2 + 512)
#define O_BT     (O_GM + 512)
#define SMEM_BYTES (O_BT + 512)           // 111616 (109 KB) -> 2 CTAs/SM

__device__ __half g_ni16[50000 * 64];     // node_inv in fp16
__device__ __half g_Wt16[49152];          // W1^T [128][256] ++ W2^T [128][128]

__device__ __forceinline__ void mma16(float* d, const uint32_t* a,
                                      uint32_t b0, uint32_t b1) {
    asm volatile(
        "mma.sync.aligned.m16n8k16.row.col.f32.f16.f16.f32 "
        "{%0,%1,%2,%3}, {%4,%5,%6,%7}, {%8,%9}, {%0,%1,%2,%3};"
        : "+f"(d[0]), "+f"(d[1]), "+f"(d[2]), "+f"(d[3])
        : "r"(a[0]), "r"(a[1]), "r"(a[2]), "r"(a[3]), "r"(b0), "r"(b1));
}

#define LDSM4(r, addr)                                                          \
    asm volatile("ldmatrix.sync.aligned.m8n8.x4.shared.b16 {%0,%1,%2,%3}, [%4];"\
        : "=r"((r)[0]), "=r"((r)[1]), "=r"((r)[2]), "=r"((r)[3]) : "r"(addr))

__device__ __forceinline__ uint32_t smem_u32(const void* p) {
    uint32_t a;
    asm("{ .reg .u64 t; cvta.to.shared.u64 t, %1; cvt.u32.u64 %0, t; }" : "=r"(a) : "l"(p));
    return a;
}
__device__ __forceinline__ void cp16(uint32_t dst, const void* src) {
    asm volatile("cp.async.cg.shared.global [%0], [%1], 16;" :: "r"(dst), "l"(src));
}
#define CP_COMMIT() asm volatile("cp.async.commit_group;" ::: "memory")
#define CP_WAIT(N)  asm volatile("cp.async.wait_group %0;" :: "n"(N) : "memory")

__global__ void prep_node(const float* __restrict__ node_inv, int n8) {
    int i = blockIdx.x * blockDim.x + threadIdx.x;   // one per 8 floats
    if (i < n8) {
        float4 v0 = ((const float4*)node_inv)[2 * i];
        float4 v1 = ((const float4*)node_inv)[2 * i + 1];
        __half2 h[4] = { __floats2half2_rn(v0.x, v0.y), __floats2half2_rn(v0.z, v0.w),
                         __floats2half2_rn(v1.x, v1.y), __floats2half2_rn(v1.z, v1.w) };
        ((uint4*)g_ni16)[i] = *(uint4*)h;
    }
}
__global__ void prep_w(const float* __restrict__ W1, const float* __restrict__ W2) {
    int i = blockIdx.x * blockDim.x + threadIdx.x;      // i = c*K + k
    if (i < 32768) {
        int c = i >> 8, k = i & 255;
        g_Wt16[i] = __float2half_rn(W1[k * HD + c]);
    } else if (i < 49152) {
        int j = i - 32768;
        int c = j >> 7, k = j & 127;
        g_Wt16[i] = __float2half_rn(W2[k * HD + c]);
    }
}

__global__ __launch_bounds__(THREADS, 2)
void edge_update_mma(const float* __restrict__ edge_features,
                     const void*  __restrict__ edge_src,
                     const void*  __restrict__ edge_dst,
                     const float* __restrict__ b1,
                     const float* __restrict__ b2,
                     const float* __restrict__ gamma,
                     const float* __restrict__ beta,
                     float* __restrict__ out,
                     int n_edges)
{
    extern __shared__ char smc[];
    __half* A16   = (__half*)(smc + O_A16);
    float2* part  = (float2*)(smc + O_PART);
    float2* stats = (float2*)(smc + O_STATS);
    int*    idxs  = (int*)(smc + O_PART);     // alias: gather phase only
    float*  cb1   = (float*)(smc + O_B1);
    float*  cb2   = (float*)(smc + O_B2);
    float*  cgm   = (float*)(smc + O_GM);
    float*  cbt   = (float*)(smc + O_BT);

    const uint32_t a16b = smem_u32(A16);
    const uint32_t wbb  = smem_u32(smc + O_W16);

    const int tid  = threadIdx.x;
    const int wid  = tid >> 5;
    const int lane = tid & 31;
    const int g    = lane >> 2;
    const int t    = lane & 3;
    const int mrow = (wid >> 2) * 64;     // 2 M-halves
    const int ncol = (wid & 3) * 32;      // 4 N-quarters
    const int wN   = wid & 3;

    const int e_base = blockIdx.x * TILE;

    // index dtype sniff (int64 buffers have zero high words)
    const int* s32c = (const int*)edge_src;
    const bool idx64 = ((s32c[1] | s32c[3] | s32c[5] | s32c[7]) == 0);

    // ---- W chunk staging: 128 rows x 64 halfs = 1024 x 16B ----
    auto stage = [&](int ch) {
        const __half* src;
        int kA, kstr;
        if (ch < 4) { src = g_Wt16;         kA = ch * 64;       kstr = 256; }
        else        { src = g_Wt16 + 32768; kA = (ch - 4) * 64; kstr = 128; }
        uint32_t dstb = wbb + (uint32_t)((ch & 1) * 128 * S_W) * 2u;
        #pragma unroll
        for (int i = 0; i < 4; ++i) {
            int idx = tid + i * THREADS;   // 0..1023
            int c   = idx >> 3;            // channel row
            int q   = idx & 7;             // 8-half quad
            cp16(dstb + (uint32_t)(c * S_W + q * 8) * 2u,
                 src + c * kstr + kA + q * 8);
        }
        CP_COMMIT();
    };
    stage(0);                               // group: s0

    if (tid < 128) {
        cb1[tid] = b1[tid];
        cb2[tid] = b2[tid];
        cgm[tid] = gamma[tid];
        cbt[tid] = beta[tid];
    }

    // ---- stage edge indices ----
    {
        int e  = tid & 127;
        int eg = e_base + e;
        if (eg >= n_edges) eg = n_edges - 1;
        const int* p = (const int*)((tid < 128) ? edge_src : edge_dst);
        idxs[tid] = idx64 ? p[2 * eg] : p[eg];
    }
    __syncthreads();

    const int eg_max = n_edges - 1;

    // ---- ef batch 0: issue 8 float4 LDGs into registers (quads 0..2047) ----
    // ef tile = 128 edges x 32 float4-quads: e = q>>5, j = q&31
    float4 efr0[8];
    #pragma unroll
    for (int it = 0; it < 8; ++it) {
        int q = tid + it * THREADS;          // 0..2047
        int e = q >> 5;
        int j = q & 31;
        int eg = e_base + e; if (eg > eg_max) eg = eg_max;
        efr0[it] = *(const float4*)(edge_features + (long long)eg * HD + j * 4);
    }

    // ---- gather gA: node halfs -> A16 cols 0..127 (16 8-half quads/edge) ----
    #pragma unroll
    for (int it = 0; it < 8; ++it) {
        int q = tid + it * THREADS;          // 0..2047
        int e = q >> 4;
        int j = q & 15;                      // 8-half quad: 0-7 src, 8-15 dst
        int node = idxs[(j < 8 ? 0 : 128) + e];
        cp16(a16b + (uint32_t)(e * S_A + j * 8) * 2u,
             g_ni16 + (long long)node * 64 + (j & 7) * 8);
    }
    CP_COMMIT();                             // group: gA

    // ---- ef batch 1: issue 8 more float4 LDGs (quads 2048..4095) ----
    float4 efr1[8];
    #pragma unroll
    for (int it = 0; it < 8; ++it) {
        int q = tid + (8 + it) * THREADS;    // 2048..4095
        int e = q >> 5;
        int j = q & 31;
        int eg = e_base + e; if (eg > eg_max) eg = eg_max;
        efr1[it] = *(const float4*)(edge_features + (long long)eg * HD + j * 4);
    }

    stage(1);                                // group: s1

    // ---- convert + store both ef batches (LDG latency now amortized) ----
    #pragma unroll
    for (int it = 0; it < 8; ++it) {
        int q = tid + it * THREADS;
        int e = q >> 5;
        int j = q & 31;
        *(__half2*)&A16[e * S_A + 128 + j * 4]     = __floats2half2_rn(efr0[it].x, efr0[it].y);
        *(__half2*)&A16[e * S_A + 128 + j * 4 + 2] = __floats2half2_rn(efr0[it].z, efr0[it].w);
    }
    #pragma unroll
    for (int it = 0; it < 8; ++it) {
        int q = tid + (8 + it) * THREADS;
        int e = q >> 5;
        int j = q & 31;
        *(__half2*)&A16[e * S_A + 128 + j * 4]     = __floats2half2_rn(efr1[it].x, efr1[it].y);
        *(__half2*)&A16[e * S_A + 128 + j * 4 + 2] = __floats2half2_rn(efr1[it].z, efr1[it].w);
    }

    // per-lane static ldmatrix byte offsets
    const uint32_t a_off = (uint32_t)((mrow + (lane & 15)) * S_A + ((lane >> 4) & 1) * 8) * 2u;
    const uint32_t b_off = (uint32_t)((ncol + (lane & 15)) * S_W + ((lane >> 4) & 1) * 8) * 2u;

    float acc[4][4][4];
    #pragma unroll
    for (int mb = 0; mb < 4; ++mb)
        #pragma unroll
        for (int nb = 0; nb < 4; ++nb)
            #pragma unroll
            for (int r = 0; r < 4; ++r) acc[mb][nb][r] = 0.f;

    // Wait ledger (stage AFTER sync):
    //  ch0: pending {s0,gA,s1} -> wait(1) drains s0,gA (needs s0,gA; ef STS is
    //       plain-store, ordered by this thread + ch2-top sync for other warps)
    //  ch1: pending {s1,s2} -> wait(1) drains s1
    //  ch2-4: wait(1);  ch5: wait(0)
    #pragma unroll 1
    for (int ch = 0; ch < 6; ++ch) {
        if (ch < 5)  CP_WAIT(1);
        else         CP_WAIT(0);
        __syncthreads();
        if (ch >= 1 && ch < 5) stage(ch + 1);

        const uint32_t wchunk = wbb + (uint32_t)((ch & 1) * 128 * S_W) * 2u;
        const int kA = (ch < 4) ? ch * 64 : (ch - 4) * 64;   // halfs
        const uint32_t abase = a16b + a_off + (uint32_t)kA * 2u;
        const uint32_t bbase = wchunk + b_off;

        #pragma unroll
        for (int ks = 0; ks < 4; ++ks) {
            const uint32_t kb = (uint32_t)(ks * 16) * 2u;
            uint32_t a[4][4], b[2][4];
            LDSM4(a[0], abase + kb);
            LDSM4(a[1], abase + (uint32_t)(16 * S_A) * 2u + kb);
            LDSM4(a[2], abase + (uint32_t)(32 * S_A) * 2u + kb);
            LDSM4(a[3], abase + (uint32_t)(48 * S_A) * 2u + kb);
            LDSM4(b[0], bbase + kb);
            LDSM4(b[1], bbase + (uint32_t)(16 * S_W) * 2u + kb);
            #pragma unroll
            for (int mb = 0; mb < 4; ++mb) {
                mma16(acc[mb][0], a[mb], b[0][0], b[0][2]);
                mma16(acc[mb][1], a[mb], b[0][1], b[0][3]);
                mma16(acc[mb][2], a[mb], b[1][0], b[1][2]);
                mma16(acc[mb][3], a[mb], b[1][1], b[1][3]);
            }
        }

        if (ch == 3) {
            // h = relu(D1 + b1) -> fp16 into A16 cols 0..127
            // (cols 0..127 last read at ch1; ch4-top sync orders vs GEMM2 reads)
            #pragma unroll
            for (int mb = 0; mb < 4; ++mb) {
                const int r0 = mrow + mb * 16 + g;
                #pragma unroll
                for (int nb = 0; nb < 4; ++nb) {
                    const int c0 = ncol + nb * 8 + 2 * t;
                    const float bb0 = cb1[c0], bb1 = cb1[c0 + 1];
                    *(__half2*)&A16[r0 * S_A + c0] =
                        __floats2half2_rn(fmaxf(acc[mb][nb][0] + bb0, 0.f),
                                          fmaxf(acc[mb][nb][1] + bb1, 0.f));
                    *(__half2*)&A16[(r0 + 8) * S_A + c0] =
                        __floats2half2_rn(fmaxf(acc[mb][nb][2] + bb0, 0.f),
                                          fmaxf(acc[mb][nb][3] + bb1, 0.f));
                }
            }
            #pragma unroll
            for (int mb = 0; mb < 4; ++mb)
                #pragma unroll
                for (int nb = 0; nb < 4; ++nb)
                    #pragma unroll
                    for (int r = 0; r < 4; ++r) acc[mb][nb][r] = 0.f;
        }
    }

    // ---- epilogue: u = D2 + b2; LayerNorm; residual; store ----
    #pragma unroll
    for (int mb = 0; mb < 4; ++mb)
        #pragma unroll
        for (int nb = 0; nb < 4; ++nb) {
            const int c0 = ncol + nb * 8 + 2 * t;
            acc[mb][nb][0] += cb2[c0];
            acc[mb][nb][1] += cb2[c0 + 1];
            acc[mb][nb][2] += cb2[c0];
            acc[mb][nb][3] += cb2[c0 + 1];
        }

    __syncthreads();   // idxs alias dead; part safe to write

    #pragma unroll
    for (int mb = 0; mb < 4; ++mb) {
        float s0 = 0.f, ss0 = 0.f, s1 = 0.f, ss1 = 0.f;
        #pragma unroll
        for (int nb = 0; nb < 4; ++nb) {
            float u0 = acc[mb][nb][0], u1 = acc[mb][nb][1];
            float u2 = acc[mb][nb][2], u3 = acc[mb][nb][3];
            s0 += u0 + u1;  ss0 += u0 * u0 + u1 * u1;
            s1 += u2 + u3;  ss1 += u2 * u2 + u3 * u3;
        }
        #pragma unroll
        for (int m = 1; m < 4; m <<= 1) {
            s0  += __shfl_xor_sync(0xffffffffu, s0,  m);
            ss0 += __shfl_xor_sync(0xffffffffu, ss0, m);
            s1  += __shfl_xor_sync(0xffffffffu, s1,  m);
            ss1 += __shfl_xor_sync(0xffffffffu, ss1, m);
        }
        if (t == 0) {
            int e0 = mrow + mb * 16 + g;
            part[e0 * 4 + wN]       = make_float2(s0, ss0);
            part[(e0 + 8) * 4 + wN] = make_float2(s1, ss1);
        }
    }
    __syncthreads();

    if (tid < TILE) {
        float s = 0.f, ss = 0.f;
        #pragma unroll
        for (int q = 0; q < 4; ++q) {
            float2 p = part[tid * 4 + q];
            s += p.x; ss += p.y;
        }
        float mu  = s * (1.f / 128.f);
        float var = ss * (1.f / 128.f) - mu * mu;
        stats[tid] = make_float2(mu, rsqrtf(var + LN_EPS));
    }
    __syncthreads();

    #pragma unroll
    for (int mb = 0; mb < 4; ++mb) {
        const int r0 = mrow + mb * 16 + g;
        const float2 st0 = stats[r0];
        const float2 st1 = stats[r0 + 8];
        const int eg0 = e_base + r0;
        const int eg1 = eg0 + 8;
        #pragma unroll
        for (int nb = 0; nb < 4; ++nb) {
            const int c0 = ncol + nb * 8 + 2 * t;
            const float gm0 = cgm[c0], gm1 = cgm[c0 + 1];
            const float bt0 = cbt[c0], bt1 = cbt[c0 + 1];
            if (eg0 < n_edges) {
                float2 ef = *(const float2*)(edge_features + (long long)eg0 * HD + c0);
                float2 o;
                o.x = ef.x + (acc[mb][nb][0] - st0.x) * st0.y * gm0 + bt0;
                o.y = ef.y + (acc[mb][nb][1] - st0.x) * st0.y * gm1 + bt1;
                *(float2*)&out[(long long)eg0 * HD + c0] = o;
            }
            if (eg1 < n_edges) {
                float2 ef = *(const float2*)(edge_features + (long long)eg1 * HD + c0);
                float2 o;
                o.x = ef.x + (acc[mb][nb][2] - st1.x) * st1.y * gm0 + bt0;
                o.y = ef.y + (acc[mb][nb][3] - st1.x) * st1.y * gm1 + bt1;
                *(float2*)&out[(long long)eg1 * HD + c0] = o;
            }
        }
    }
}

extern "C" void kernel_launch(void* const* d_in, const int* in_sizes, int n_in,
                              void* d_out, int out_size)
{
    const float* node_inv      = (const float*)d_in[0];
    const float* edge_features = (const float*)d_in[1];
    const void*  edge_src      = d_in[2];
    const void*  edge_dst      = d_in[3];
    const float* W1            = (const float*)d_in[4];
    const float* b1            = (const float*)d_in[5];
    const float* W2            = (const float*)d_in[6];
    const float* b2            = (const float*)d_in[7];
    const float* gamma         = (const float*)d_in[8];
    const float* beta          = (const float*)d_in[9];
    float* out = (float*)d_out;

    int n_edges = in_sizes[1] / HD;
    int n_node_elems = in_sizes[0];
    if (n_node_elems > 50000 * 64) n_node_elems = 50000 * 64;
    int n8 = n_node_elems / 8;

    prep_node<<<(n8 + 255) / 256, 256>>>(node_inv, n8);
    prep_w<<<(49152 + 255) / 256, 256>>>(W1, W2);

    cudaFuncSetAttribute(edge_update_mma,
                         cudaFuncAttributeMaxDynamicSharedMemorySize, SMEM_BYTES);

    int grid = (n_edges + TILE - 1) / TILE;
    edge_update_mma<<<grid, THREADS, SMEM_BYTES>>>(
        edge_features, edge_src, edge_dst,
        b1, b2, gamma, beta, out, n_edges);
}

// round 16
// speedup vs baseline: 1.1014x; 1.0663x over previous
#include <cuda_runtime.h>
#include <cuda_fp16.h>
#include <cstdint>

// ============================================================================
// EdgeUpdate, round 15: exact R11 mainloop (best measured: 395us) +
// vectorized single prep kernel (node fp16 convert + W^T fp16 convert).
//  - 256 threads/CTA, 8 warps, warp tile 64 edges x 32 channels, 2 CTAs/SM
//  - node gather: cp.async from fp16 g_ni16; ef: LDG fp32 -> cvt -> STS fp16
//  - residual: exact fp32 edge_features re-read from gmem (L2-hot) in epilogue
//  - fragments via ldmatrix.m8n8.x4.b16; mma.m16n8k16.f32.f16
// ============================================================================

#define THREADS   256
#define TILE      128
#define HD        128
#define LN_EPS    1e-5f
#define S_A       264     // A16 row stride (halfs)
#define S_W       72      // W chunk row stride (halfs)

// smem byte offsets
#define O_A16    0
#define O_W16    67584                    // 128*264*2
#define O_PART   (O_W16 + 36864)          // 104448 (float2[128][4]) / idxs alias
#define O_STATS  (O_PART + 4096)          // 108544 (float2[128])
#define O_B1     (O_STATS + 1024)         // 109568
#define O_B2     (O_B1 + 512)
#define O_GM     (O_B2 + 512)
#define O_BT     (O_GM + 512)
#define SMEM_BYTES (O_BT + 512)           // 111616 (109 KB) -> 2 CTAs/SM

__device__ __half g_ni16[50000 * 64];     // node_inv in fp16
__device__ __half g_Wt16[49152];          // W1^T [128][256] ++ W2^T [128][128]

__device__ __forceinline__ void mma16(float* d, const uint32_t* a,
                                      uint32_t b0, uint32_t b1) {
    asm volatile(
        "mma.sync.aligned.m16n8k16.row.col.f32.f16.f16.f32 "
        "{%0,%1,%2,%3}, {%4,%5,%6,%7}, {%8,%9}, {%0,%1,%2,%3};"
        : "+f"(d[0]), "+f"(d[1]), "+f"(d[2]), "+f"(d[3])
        : "r"(a[0]), "r"(a[1]), "r"(a[2]), "r"(a[3]), "r"(b0), "r"(b1));
}

#define LDSM4(r, addr)                                                          \
    asm volatile("ldmatrix.sync.aligned.m8n8.x4.shared.b16 {%0,%1,%2,%3}, [%4];"\
        : "=r"((r)[0]), "=r"((r)[1]), "=r"((r)[2]), "=r"((r)[3]) : "r"(addr))

__device__ __forceinline__ uint32_t smem_u32(const void* p) {
    uint32_t a;
    asm("{ .reg .u64 t; cvta.to.shared.u64 t, %1; cvt.u32.u64 %0, t; }" : "=r"(a) : "l"(p));
    return a;
}
__device__ __forceinline__ void cp16(uint32_t dst, const void* src) {
    asm volatile("cp.async.cg.shared.global [%0], [%1], 16;" :: "r"(dst), "l"(src));
}
#define CP_COMMIT() asm volatile("cp.async.commit_group;" ::: "memory")
#define CP_WAIT(N)  asm volatile("cp.async.wait_group %0;" :: "n"(N) : "memory")

// One prep kernel: vectorized node_inv fp16 convert + W^T fp16 convert.
__global__ void prep_all(const float* __restrict__ node_inv, int n8,
                         const float* __restrict__ W1, const float* __restrict__ W2) {
    int i = blockIdx.x * blockDim.x + threadIdx.x;
    if (i < n8) {
        float4 v0 = ((const float4*)node_inv)[2 * i];
        float4 v1 = ((const float4*)node_inv)[2 * i + 1];
        __half2 h[4] = { __floats2half2_rn(v0.x, v0.y), __floats2half2_rn(v0.z, v0.w),
                         __floats2half2_rn(v1.x, v1.y), __floats2half2_rn(v1.z, v1.w) };
        ((uint4*)g_ni16)[i] = *(uint4*)h;
    }
    if (i < 32768) {
        int c = i >> 8, k = i & 255;
        g_Wt16[i] = __float2half_rn(W1[k * HD + c]);
    } else if (i < 49152) {
        int j = i - 32768;
        int c = j >> 7, k = j & 127;
        g_Wt16[i] = __float2half_rn(W2[k * HD + c]);
    }
}

__global__ __launch_bounds__(THREADS, 2)
void edge_update_mma(const float* __restrict__ edge_features,
                     const void*  __restrict__ edge_src,
                     const void*  __restrict__ edge_dst,
                     const float* __restrict__ b1,
                     const float* __restrict__ b2,
                     const float* __restrict__ gamma,
                     const float* __restrict__ beta,
                     float* __restrict__ out,
                     int n_edges)
{
    extern __shared__ char smc[];
    __half* A16   = (__half*)(smc + O_A16);
    float2* part  = (float2*)(smc + O_PART);
    float2* stats = (float2*)(smc + O_STATS);
    int*    idxs  = (int*)(smc + O_PART);     // alias: gather phase only
    float*  cb1   = (float*)(smc + O_B1);
    float*  cb2   = (float*)(smc + O_B2);
    float*  cgm   = (float*)(smc + O_GM);
    float*  cbt   = (float*)(smc + O_BT);

    const uint32_t a16b = smem_u32(A16);
    const uint32_t wbb  = smem_u32(smc + O_W16);

    const int tid  = threadIdx.x;
    const int wid  = tid >> 5;
    const int lane = tid & 31;
    const int g    = lane >> 2;
    const int t    = lane & 3;
    const int mrow = (wid >> 2) * 64;     // 2 M-halves
    const int ncol = (wid & 3) * 32;      // 4 N-quarters
    const int wN   = wid & 3;

    const int e_base = blockIdx.x * TILE;

    // index dtype sniff (int64 buffers have zero high words)
    const int* s32c = (const int*)edge_src;
    const bool idx64 = ((s32c[1] | s32c[3] | s32c[5] | s32c[7]) == 0);

    // ---- W chunk staging: 128 rows x 64 halfs = 1024 x 16B ----
    auto stage = [&](int ch) {
        const __half* src;
        int kA, kstr;
        if (ch < 4) { src = g_Wt16;         kA = ch * 64;       kstr = 256; }
        else        { src = g_Wt16 + 32768; kA = (ch - 4) * 64; kstr = 128; }
        uint32_t dstb = wbb + (uint32_t)((ch & 1) * 128 * S_W) * 2u;
        #pragma unroll
        for (int i = 0; i < 4; ++i) {
            int idx = tid + i * THREADS;   // 0..1023
            int c   = idx >> 3;            // channel row
            int q   = idx & 7;             // 8-half quad
            cp16(dstb + (uint32_t)(c * S_W + q * 8) * 2u,
                 src + c * kstr + kA + q * 8);
        }
        CP_COMMIT();
    };
    stage(0);                               // group: s0

    if (tid < 128) {
        cb1[tid] = b1[tid];
        cb2[tid] = b2[tid];
        cgm[tid] = gamma[tid];
        cbt[tid] = beta[tid];
    }

    // ---- stage edge indices ----
    {
        int e  = tid & 127;
        int eg = e_base + e;
        if (eg >= n_edges) eg = n_edges - 1;
        const int* p = (const int*)((tid < 128) ? edge_src : edge_dst);
        idxs[tid] = idx64 ? p[2 * eg] : p[eg];
    }
    __syncthreads();

    // ---- gather gA: node halfs -> A16 cols 0..127 (16B = 8 halfs) ----
    #pragma unroll
    for (int it = 0; it < 8; ++it) {
        int q = tid + it * THREADS;          // 0..2047
        int e = q >> 4;
        int j = q & 15;                      // 8-half quad: 0-7 src, 8-15 dst
        int node = idxs[(j < 8 ? 0 : 128) + e];
        cp16(a16b + (uint32_t)(e * S_A + j * 8) * 2u,
             g_ni16 + (long long)node * 64 + (j & 7) * 8);
    }
    CP_COMMIT();                             // group: gA

    stage(1);                                // group: s1

    // ---- ef: LDG fp32 -> cvt -> STS fp16 into A16 cols 128..255 ----
    {
        int eg_max = n_edges - 1;
        #pragma unroll 4
        for (int it = 0; it < 16; ++it) {
            int q = tid + it * THREADS;      // 0..4095
            int e = q >> 5;
            int j = q & 31;                  // 4-float quad
            int eg = e_base + e; if (eg > eg_max) eg = eg_max;
            float4 v = *(const float4*)(edge_features + (long long)eg * HD + j * 4);
            __half2 h01 = __floats2half2_rn(v.x, v.y);
            __half2 h23 = __floats2half2_rn(v.z, v.w);
            *(__half2*)&A16[e * S_A + 128 + j * 4]     = h01;
            *(__half2*)&A16[e * S_A + 128 + j * 4 + 2] = h23;
        }
    }

    // per-lane static ldmatrix byte offsets
    const uint32_t a_off = (uint32_t)((mrow + (lane & 15)) * S_A + ((lane >> 4) & 1) * 8) * 2u;
    const uint32_t b_off = (uint32_t)((ncol + (lane & 15)) * S_W + ((lane >> 4) & 1) * 8) * 2u;

    float acc[4][4][4];
    #pragma unroll
    for (int mb = 0; mb < 4; ++mb)
        #pragma unroll
        for (int nb = 0; nb < 4; ++nb)
            #pragma unroll
            for (int r = 0; r < 4; ++r) acc[mb][nb][r] = 0.f;

    // Wait ledger (stage AFTER sync):
    //  ch0: pending {s0,gA,s1} -> wait(1) drains s0,gA (needs s0,gA; ef STS is
    //       plain-store, ordered by this thread + ch2-top sync for other warps)
    //  ch1: pending {s1,s2} -> wait(1) drains s1
    //  ch2-4: wait(1);  ch5: wait(0)
    #pragma unroll 1
    for (int ch = 0; ch < 6; ++ch) {
        if (ch < 5)  CP_WAIT(1);
        else         CP_WAIT(0);
        __syncthreads();
        if (ch >= 1 && ch < 5) stage(ch + 1);

        const uint32_t wchunk = wbb + (uint32_t)((ch & 1) * 128 * S_W) * 2u;
        const int kA = (ch < 4) ? ch * 64 : (ch - 4) * 64;   // halfs
        const uint32_t abase = a16b + a_off + (uint32_t)kA * 2u;
        const uint32_t bbase = wchunk + b_off;

        #pragma unroll
        for (int ks = 0; ks < 4; ++ks) {
            const uint32_t kb = (uint32_t)(ks * 16) * 2u;
            uint32_t a[4][4], b[2][4];
            LDSM4(a[0], abase + kb);
            LDSM4(a[1], abase + (uint32_t)(16 * S_A) * 2u + kb);
            LDSM4(a[2], abase + (uint32_t)(32 * S_A) * 2u + kb);
            LDSM4(a[3], abase + (uint32_t)(48 * S_A) * 2u + kb);
            LDSM4(b[0], bbase + kb);
            LDSM4(b[1], bbase + (uint32_t)(16 * S_W) * 2u + kb);
            #pragma unroll
            for (int mb = 0; mb < 4; ++mb) {
                mma16(acc[mb][0], a[mb], b[0][0], b[0][2]);
                mma16(acc[mb][1], a[mb], b[0][1], b[0][3]);
                mma16(acc[mb][2], a[mb], b[1][0], b[1][2]);
                mma16(acc[mb][3], a[mb], b[1][1], b[1][3]);
            }
        }

        if (ch == 3) {
            // h = relu(D1 + b1) -> fp16 into A16 cols 0..127
            // (cols 0..127 last read at ch1; ch4-top sync orders vs GEMM2 reads)
            #pragma unroll
            for (int mb = 0; mb < 4; ++mb) {
                const int r0 = mrow + mb * 16 + g;
                #pragma unroll
                for (int nb = 0; nb < 4; ++nb) {
                    const int c0 = ncol + nb * 8 + 2 * t;
                    const float bb0 = cb1[c0], bb1 = cb1[c0 + 1];
                    *(__half2*)&A16[r0 * S_A + c0] =
                        __floats2half2_rn(fmaxf(acc[mb][nb][0] + bb0, 0.f),
                                          fmaxf(acc[mb][nb][1] + bb1, 0.f));
                    *(__half2*)&A16[(r0 + 8) * S_A + c0] =
                        __floats2half2_rn(fmaxf(acc[mb][nb][2] + bb0, 0.f),
                                          fmaxf(acc[mb][nb][3] + bb1, 0.f));
                }
            }
            #pragma unroll
            for (int mb = 0; mb < 4; ++mb)
                #pragma unroll
                for (int nb = 0; nb < 4; ++nb)
                    #pragma unroll
                    for (int r = 0; r < 4; ++r) acc[mb][nb][r] = 0.f;
        }
    }

    // ---- epilogue: u = D2 + b2; LayerNorm; residual; store ----
    #pragma unroll
    for (int mb = 0; mb < 4; ++mb)
        #pragma unroll
        for (int nb = 0; nb < 4; ++nb) {
            const int c0 = ncol + nb * 8 + 2 * t;
            acc[mb][nb][0] += cb2[c0];
            acc[mb][nb][1] += cb2[c0 + 1];
            acc[mb][nb][2] += cb2[c0];
            acc[mb][nb][3] += cb2[c0 + 1];
        }

    __syncthreads();   // idxs alias dead; part safe to write

    #pragma unroll
    for (int mb = 0; mb < 4; ++mb) {
        float s0 = 0.f, ss0 = 0.f, s1 = 0.f, ss1 = 0.f;
        #pragma unroll
        for (int nb = 0; nb < 4; ++nb) {
            float u0 = acc[mb][nb][0], u1 = acc[mb][nb][1];
            float u2 = acc[mb][nb][2], u3 = acc[mb][nb][3];
            s0 += u0 + u1;  ss0 += u0 * u0 + u1 * u1;
            s1 += u2 + u3;  ss1 += u2 * u2 + u3 * u3;
        }
        #pragma unroll
        for (int m = 1; m < 4; m <<= 1) {
            s0  += __shfl_xor_sync(0xffffffffu, s0,  m);
            ss0 += __shfl_xor_sync(0xffffffffu, ss0, m);
            s1  += __shfl_xor_sync(0xffffffffu, s1,  m);
            ss1 += __shfl_xor_sync(0xffffffffu, ss1, m);
        }
        if (t == 0) {
            int e0 = mrow + mb * 16 + g;
            part[e0 * 4 + wN]       = make_float2(s0, ss0);
            part[(e0 + 8) * 4 + wN] = make_float2(s1, ss1);
        }
    }
    __syncthreads();

    if (tid < TILE) {
        float s = 0.f, ss = 0.f;
        #pragma unroll
        for (int q = 0; q < 4; ++q) {
            float2 p = part[tid * 4 + q];
            s += p.x; ss += p.y;
        }
        float mu  = s * (1.f / 128.f);
        float var = ss * (1.f / 128.f) - mu * mu;
        stats[tid] = make_float2(mu, rsqrtf(var + LN_EPS));
    }
    __syncthreads();

    #pragma unroll
    for (int mb = 0; mb < 4; ++mb) {
        const int r0 = mrow + mb * 16 + g;
        const float2 st0 = stats[r0];
        const float2 st1 = stats[r0 + 8];
        const int eg0 = e_base + r0;
        const int eg1 = eg0 + 8;
        #pragma unroll
        for (int nb = 0; nb < 4; ++nb) {
            const int c0 = ncol + nb * 8 + 2 * t;
            const float gm0 = cgm[c0], gm1 = cgm[c0 + 1];
            const float bt0 = cbt[c0], bt1 = cbt[c0 + 1];
            if (eg0 < n_edges) {
                float2 ef = *(const float2*)(edge_features + (long long)eg0 * HD + c0);
                float2 o;
                o.x = ef.x + (acc[mb][nb][0] - st0.x) * st0.y * gm0 + bt0;
                o.y = ef.y + (acc[mb][nb][1] - st0.x) * st0.y * gm1 + bt1;
                *(float2*)&out[(long long)eg0 * HD + c0] = o;
            }
            if (eg1 < n_edges) {
                float2 ef = *(const float2*)(edge_features + (long long)eg1 * HD + c0);
                float2 o;
                o.x = ef.x + (acc[mb][nb][2] - st1.x) * st1.y * gm0 + bt0;
                o.y = ef.y + (acc[mb][nb][3] - st1.x) * st1.y * gm1 + bt1;
                *(float2*)&out[(long long)eg1 * HD + c0] = o;
            }
        }
    }
}

extern "C" void kernel_launch(void* const* d_in, const int* in_sizes, int n_in,
                              void* d_out, int out_size)
{
    const float* node_inv      = (const float*)d_in[0];
    const float* edge_features = (const float*)d_in[1];
    const void*  edge_src      = d_in[2];
    const void*  edge_dst      = d_in[3];
    const float* W1            = (const float*)d_in[4];
    const float* b1            = (const float*)d_in[5];
    const float* W2            = (const float*)d_in[6];
    const float* b2            = (const float*)d_in[7];
    const float* gamma         = (const float*)d_in[8];
    const float* beta          = (const float*)d_in[9];
    float* out = (float*)d_out;

    int n_edges = in_sizes[1] / HD;
    int n_node_elems = in_sizes[0];
    if (n_node_elems > 50000 * 64) n_node_elems = 50000 * 64;
    int n8 = n_node_elems / 8;

    int prep_n = n8 > 49152 ? n8 : 49152;
    prep_all<<<(prep_n + 255) / 256, 256>>>(node_inv, n8, W1, W2);

    cudaFuncSetAttribute(edge_update_mma,
                         cudaFuncAttributeMaxDynamicSharedMemorySize, SMEM_BYTES);

    int grid = (n_edges + TILE - 1) / TILE;
    edge_update_mma<<<grid, THREADS, SMEM_BYTES>>>(
        edge_features, edge_src, edge_dst,
        b1, b2, gamma, beta, out, n_edges);
}

// round 17
// speedup vs baseline: 1.2634x; 1.1471x over previous
#include <cuda_runtime.h>
#include <cuda_fp16.h>
#include <cstdint>

// ============================================================================
// EdgeUpdate, round 16: R15 + residual taken from the fp16 ef copy in A16
// (no second edge_features LDG pass) + full-tile fast paths (no clamps,
// 32-bit hoisted addressing).
//  - 256 threads/CTA, 8 warps, warp tile 64 edges x 32 channels, 2 CTAs/SM
//  - node gather: cp.async from fp16 g_ni16; ef: LDG fp32 -> cvt -> STS fp16
//  - fragments via ldmatrix.m8n8.x4.b16; mma.m16n8k16.f32.f16
// ============================================================================

#define THREADS   256
#define TILE      128
#define HD        128
#define LN_EPS    1e-5f
#define S_A       264     // A16 row stride (halfs)
#define S_W       72      // W chunk row stride (halfs)

// smem byte offsets
#define O_A16    0
#define O_W16    67584                    // 128*264*2
#define O_PART   (O_W16 + 36864)          // 104448 (float2[128][4]) / idxs alias
#define O_STATS  (O_PART + 4096)          // 108544 (float2[128])
#define O_B1     (O_STATS + 1024)         // 109568
#define O_B2     (O_B1 + 512)
#define O_GM     (O_B2 + 512)
#define O_BT     (O_GM + 512)
#define SMEM_BYTES (O_BT + 512)           // 111616 (109 KB) -> 2 CTAs/SM

__device__ __half g_ni16[50000 * 64];     // node_inv in fp16
__device__ __half g_Wt16[49152];          // W1^T [128][256] ++ W2^T [128][128]

__device__ __forceinline__ void mma16(float* d, const uint32_t* a,
                                      uint32_t b0, uint32_t b1) {
    asm volatile(
        "mma.sync.aligned.m16n8k16.row.col.f32.f16.f16.f32 "
        "{%0,%1,%2,%3}, {%4,%5,%6,%7}, {%8,%9}, {%0,%1,%2,%3};"
        : "+f"(d[0]), "+f"(d[1]), "+f"(d[2]), "+f"(d[3])
        : "r"(a[0]), "r"(a[1]), "r"(a[2]), "r"(a[3]), "r"(b0), "r"(b1));
}

#define LDSM4(r, addr)                                                          \
    asm volatile("ldmatrix.sync.aligned.m8n8.x4.shared.b16 {%0,%1,%2,%3}, [%4];"\
        : "=r"((r)[0]), "=r"((r)[1]), "=r"((r)[2]), "=r"((r)[3]) : "r"(addr))

__device__ __forceinline__ uint32_t smem_u32(const void* p) {
    uint32_t a;
    asm("{ .reg .u64 t; cvta.to.shared.u64 t, %1; cvt.u32.u64 %0, t; }" : "=r"(a) : "l"(p));
    return a;
}
__device__ __forceinline__ void cp16(uint32_t dst, const void* src) {
    asm volatile("cp.async.cg.shared.global [%0], [%1], 16;" :: "r"(dst), "l"(src));
}
#define CP_COMMIT() asm volatile("cp.async.commit_group;" ::: "memory")
#define CP_WAIT(N)  asm volatile("cp.async.wait_group %0;" :: "n"(N) : "memory")

// One prep kernel: vectorized node_inv fp16 convert + W^T fp16 convert.
__global__ void prep_all(const float* __restrict__ node_inv, int n8,
                         const float* __restrict__ W1, const float* __restrict__ W2) {
    int i = blockIdx.x * blockDim.x + threadIdx.x;
    if (i < n8) {
        float4 v0 = ((const float4*)node_inv)[2 * i];
        float4 v1 = ((const float4*)node_inv)[2 * i + 1];
        __half2 h[4] = { __floats2half2_rn(v0.x, v0.y), __floats2half2_rn(v0.z, v0.w),
                         __floats2half2_rn(v1.x, v1.y), __floats2half2_rn(v1.z, v1.w) };
        ((uint4*)g_ni16)[i] = *(uint4*)h;
    }
    if (i < 32768) {
        int c = i >> 8, k = i & 255;
        g_Wt16[i] = __float2half_rn(W1[k * HD + c]);
    } else if (i < 49152) {
        int j = i - 32768;
        int c = j >> 7, k = j & 127;
        g_Wt16[i] = __float2half_rn(W2[k * HD + c]);
    }
}

__global__ __launch_bounds__(THREADS, 2)
void edge_update_mma(const float* __restrict__ edge_features,
                     const void*  __restrict__ edge_src,
                     const void*  __restrict__ edge_dst,
                     const float* __restrict__ b1,
                     const float* __restrict__ b2,
                     const float* __restrict__ gamma,
                     const float* __restrict__ beta,
                     float* __restrict__ out,
                     int n_edges)
{
    extern __shared__ char smc[];
    __half* A16   = (__half*)(smc + O_A16);
    float2* part  = (float2*)(smc + O_PART);
    float2* stats = (float2*)(smc + O_STATS);
    int*    idxs  = (int*)(smc + O_PART);     // alias: gather phase only
    float*  cb1   = (float*)(smc + O_B1);
    float*  cb2   = (float*)(smc + O_B2);
    float*  cgm   = (float*)(smc + O_GM);
    float*  cbt   = (float*)(smc + O_BT);

    const uint32_t a16b = smem_u32(A16);
    const uint32_t wbb  = smem_u32(smc + O_W16);

    const int tid  = threadIdx.x;
    const int wid  = tid >> 5;
    const int lane = tid & 31;
    const int g    = lane >> 2;
    const int t    = lane & 3;
    const int mrow = (wid >> 2) * 64;     // 2 M-halves
    const int ncol = (wid & 3) * 32;      // 4 N-quarters
    const int wN   = wid & 3;

    const int e_base = blockIdx.x * TILE;
    const bool full  = (e_base + TILE) <= n_edges;   // whole tile in range

    // index dtype sniff (int64 buffers have zero high words)
    const int* s32c = (const int*)edge_src;
    const bool idx64 = ((s32c[1] | s32c[3] | s32c[5] | s32c[7]) == 0);

    // ---- W chunk staging: 128 rows x 64 halfs = 1024 x 16B ----
    auto stage = [&](int ch) {
        const __half* src;
        int kA, kstr;
        if (ch < 4) { src = g_Wt16;         kA = ch * 64;       kstr = 256; }
        else        { src = g_Wt16 + 32768; kA = (ch - 4) * 64; kstr = 128; }
        uint32_t dstb = wbb + (uint32_t)((ch & 1) * 128 * S_W) * 2u;
        #pragma unroll
        for (int i = 0; i < 4; ++i) {
            int idx = tid + i * THREADS;   // 0..1023
            int c   = idx >> 3;            // channel row
            int q   = idx & 7;             // 8-half quad
            cp16(dstb + (uint32_t)(c * S_W + q * 8) * 2u,
                 src + c * kstr + kA + q * 8);
        }
        CP_COMMIT();
    };
    stage(0);                               // group: s0

    if (tid < 128) {
        cb1[tid] = b1[tid];
        cb2[tid] = b2[tid];
        cgm[tid] = gamma[tid];
        cbt[tid] = beta[tid];
    }

    // ---- stage edge indices ----
    {
        int e  = tid & 127;
        int eg = e_base + e;
        if (eg >= n_edges) eg = n_edges - 1;
        const int* p = (const int*)((tid < 128) ? edge_src : edge_dst);
        idxs[tid] = idx64 ? p[2 * eg] : p[eg];
    }
    __syncthreads();

    // ---- gather gA: node halfs -> A16 cols 0..127 (16B = 8 halfs) ----
    #pragma unroll
    for (int it = 0; it < 8; ++it) {
        int q = tid + it * THREADS;          // 0..2047
        int e = q >> 4;
        int j = q & 15;                      // 8-half quad: 0-7 src, 8-15 dst
        int node = idxs[(j < 8 ? 0 : 128) + e];
        cp16(a16b + (uint32_t)(e * S_A + j * 8) * 2u,
             g_ni16 + (long long)node * 64 + (j & 7) * 8);
    }
    CP_COMMIT();                             // group: gA

    stage(1);                                // group: s1

    // ---- ef: LDG fp32 -> cvt -> STS fp16 into A16 cols 128..255 ----
    if (full) {
        const float* efp = edge_features + (long long)e_base * HD;
        #pragma unroll 4
        for (int it = 0; it < 16; ++it) {
            int q = tid + it * THREADS;      // 0..4095; src offset = 4q floats
            float4 v = *(const float4*)(efp + (uint32_t)q * 4u);
            int e = q >> 5;
            int j = q & 31;
            *(__half2*)&A16[e * S_A + 128 + j * 4]     = __floats2half2_rn(v.x, v.y);
            *(__half2*)&A16[e * S_A + 128 + j * 4 + 2] = __floats2half2_rn(v.z, v.w);
        }
    } else {
        int eg_max = n_edges - 1;
        #pragma unroll 4
        for (int it = 0; it < 16; ++it) {
            int q = tid + it * THREADS;
            int e = q >> 5;
            int j = q & 31;
            int eg = e_base + e; if (eg > eg_max) eg = eg_max;
            float4 v = *(const float4*)(edge_features + (long long)eg * HD + j * 4);
            *(__half2*)&A16[e * S_A + 128 + j * 4]     = __floats2half2_rn(v.x, v.y);
            *(__half2*)&A16[e * S_A + 128 + j * 4 + 2] = __floats2half2_rn(v.z, v.w);
        }
    }

    // per-lane static ldmatrix byte offsets
    const uint32_t a_off = (uint32_t)((mrow + (lane & 15)) * S_A + ((lane >> 4) & 1) * 8) * 2u;
    const uint32_t b_off = (uint32_t)((ncol + (lane & 15)) * S_W + ((lane >> 4) & 1) * 8) * 2u;

    float acc[4][4][4];
    #pragma unroll
    for (int mb = 0; mb < 4; ++mb)
        #pragma unroll
        for (int nb = 0; nb < 4; ++nb)
            #pragma unroll
            for (int r = 0; r < 4; ++r) acc[mb][nb][r] = 0.f;

    // Wait ledger (stage AFTER sync):
    //  ch0: pending {s0,gA,s1} -> wait(1) drains s0,gA
    //  ch1-4: wait(1);  ch5: wait(0)
    #pragma unroll 1
    for (int ch = 0; ch < 6; ++ch) {
        if (ch < 5)  CP_WAIT(1);
        else         CP_WAIT(0);
        __syncthreads();
        if (ch >= 1 && ch < 5) stage(ch + 1);

        const uint32_t wchunk = wbb + (uint32_t)((ch & 1) * 128 * S_W) * 2u;
        const int kA = (ch < 4) ? ch * 64 : (ch - 4) * 64;   // halfs
        const uint32_t abase = a16b + a_off + (uint32_t)kA * 2u;
        const uint32_t bbase = wchunk + b_off;

        #pragma unroll
        for (int ks = 0; ks < 4; ++ks) {
            const uint32_t kb = (uint32_t)(ks * 16) * 2u;
            uint32_t a[4][4], b[2][4];
            LDSM4(a[0], abase + kb);
            LDSM4(a[1], abase + (uint32_t)(16 * S_A) * 2u + kb);
            LDSM4(a[2], abase + (uint32_t)(32 * S_A) * 2u + kb);
            LDSM4(a[3], abase + (uint32_t)(48 * S_A) * 2u + kb);
            LDSM4(b[0], bbase + kb);
            LDSM4(b[1], bbase + (uint32_t)(16 * S_W) * 2u + kb);
            #pragma unroll
            for (int mb = 0; mb < 4; ++mb) {
                mma16(acc[mb][0], a[mb], b[0][0], b[0][2]);
                mma16(acc[mb][1], a[mb], b[0][1], b[0][3]);
                mma16(acc[mb][2], a[mb], b[1][0], b[1][2]);
                mma16(acc[mb][3], a[mb], b[1][1], b[1][3]);
            }
        }

        if (ch == 3) {
            // h = relu(D1 + b1) -> fp16 into A16 cols 0..127
            // (cols 0..127 last read at ch1; ch4-top sync orders vs GEMM2 reads)
            #pragma unroll
            for (int mb = 0; mb < 4; ++mb) {
                const int r0 = mrow + mb * 16 + g;
                #pragma unroll
                for (int nb = 0; nb < 4; ++nb) {
                    const int c0 = ncol + nb * 8 + 2 * t;
                    const float bb0 = cb1[c0], bb1 = cb1[c0 + 1];
                    *(__half2*)&A16[r0 * S_A + c0] =
                        __floats2half2_rn(fmaxf(acc[mb][nb][0] + bb0, 0.f),
                                          fmaxf(acc[mb][nb][1] + bb1, 0.f));
                    *(__half2*)&A16[(r0 + 8) * S_A + c0] =
                        __floats2half2_rn(fmaxf(acc[mb][nb][2] + bb0, 0.f),
                                          fmaxf(acc[mb][nb][3] + bb1, 0.f));
                }
            }
            #pragma unroll
            for (int mb = 0; mb < 4; ++mb)
                #pragma unroll
                for (int nb = 0; nb < 4; ++nb)
                    #pragma unroll
                    for (int r = 0; r < 4; ++r) acc[mb][nb][r] = 0.f;
        }
    }

    // ---- epilogue: u = D2 + b2; LayerNorm; residual (fp16 ef in A16); store ----
    #pragma unroll
    for (int mb = 0; mb < 4; ++mb)
        #pragma unroll
        for (int nb = 0; nb < 4; ++nb) {
            const int c0 = ncol + nb * 8 + 2 * t;
            acc[mb][nb][0] += cb2[c0];
            acc[mb][nb][1] += cb2[c0 + 1];
            acc[mb][nb][2] += cb2[c0];
            acc[mb][nb][3] += cb2[c0 + 1];
        }

    __syncthreads();   // idxs alias dead; part safe to write

    #pragma unroll
    for (int mb = 0; mb < 4; ++mb) {
        float s0 = 0.f, ss0 = 0.f, s1 = 0.f, ss1 = 0.f;
        #pragma unroll
        for (int nb = 0; nb < 4; ++nb) {
            float u0 = acc[mb][nb][0], u1 = acc[mb][nb][1];
            float u2 = acc[mb][nb][2], u3 = acc[mb][nb][3];
            s0 += u0 + u1;  ss0 += u0 * u0 + u1 * u1;
            s1 += u2 + u3;  ss1 += u2 * u2 + u3 * u3;
        }
        #pragma unroll
        for (int m = 1; m < 4; m <<= 1) {
            s0  += __shfl_xor_sync(0xffffffffu, s0,  m);
            ss0 += __shfl_xor_sync(0xffffffffu, ss0, m);
            s1  += __shfl_xor_sync(0xffffffffu, s1,  m);
            ss1 += __shfl_xor_sync(0xffffffffu, ss1, m);
        }
        if (t == 0) {
            int e0 = mrow + mb * 16 + g;
            part[e0 * 4 + wN]       = make_float2(s0, ss0);
            part[(e0 + 8) * 4 + wN] = make_float2(s1, ss1);
        }
    }
    __syncthreads();

    if (tid < TILE) {
        float s = 0.f, ss = 0.f;
        #pragma unroll
        for (int q = 0; q < 4; ++q) {
            float2 p = part[tid * 4 + q];
            s += p.x; ss += p.y;
        }
        float mu  = s * (1.f / 128.f);
        float var = ss * (1.f / 128.f) - mu * mu;
        stats[tid] = make_float2(mu, rsqrtf(var + LN_EPS));
    }
    __syncthreads();

    float* outp = out + (long long)e_base * HD;   // 32-bit offsets within tile

    #pragma unroll
    for (int mb = 0; mb < 4; ++mb) {
        const int r0 = mrow + mb * 16 + g;
        const float2 st0 = stats[r0];
        const float2 st1 = stats[r0 + 8];
        const bool ok0 = full || (e_base + r0     < n_edges);
        const bool ok1 = full || (e_base + r0 + 8 < n_edges);
        #pragma unroll
        for (int nb = 0; nb < 4; ++nb) {
            const int c0 = ncol + nb * 8 + 2 * t;
            const float gm0 = cgm[c0], gm1 = cgm[c0 + 1];
            const float bt0 = cbt[c0], bt1 = cbt[c0 + 1];
            if (ok0) {
                float2 ef = __half22float2(*(const __half2*)&A16[r0 * S_A + 128 + c0]);
                float2 o;
                o.x = ef.x + (acc[mb][nb][0] - st0.x) * st0.y * gm0 + bt0;
                o.y = ef.y + (acc[mb][nb][1] - st0.x) * st0.y * gm1 + bt1;
                *(float2*)&outp[r0 * HD + c0] = o;
            }
            if (ok1) {
                float2 ef = __half22float2(*(const __half2*)&A16[(r0 + 8) * S_A + 128 + c0]);
                float2 o;
                o.x = ef.x + (acc[mb][nb][2] - st1.x) * st1.y * gm0 + bt0;
                o.y = ef.y + (acc[mb][nb][3] - st1.x) * st1.y * gm1 + bt1;
                *(float2*)&outp[(r0 + 8) * HD + c0] = o;
            }
        }
    }
}

extern "C" void kernel_launch(void* const* d_in, const int* in_sizes, int n_in,
                              void* d_out, int out_size)
{
    const float* node_inv      = (const float*)d_in[0];
    const float* edge_features = (const float*)d_in[1];
    const void*  edge_src      = d_in[2];
    const void*  edge_dst      = d_in[3];
    const float* W1            = (const float*)d_in[4];
    const float* b1            = (const float*)d_in[5];
    const float* W2            = (const float*)d_in[6];
    const float* b2            = (const float*)d_in[7];
    const float* gamma         = (const float*)d_in[8];
    const float* beta          = (const float*)d_in[9];
    float* out = (float*)d_out;

    int n_edges = in_sizes[1] / HD;
    int n_node_elems = in_sizes[0];
    if (n_node_elems > 50000 * 64) n_node_elems = 50000 * 64;
    int n8 = n_node_elems / 8;

    int prep_n = n8 > 49152 ? n8 : 49152;
    prep_all<<<(prep_n + 255) / 256, 256>>>(node_inv, n8, W1, W2);

    cudaFuncSetAttribute(edge_update_mma,
                         cudaFuncAttributeMaxDynamicSharedMemorySize, SMEM_BYTES);

    int grid = (n_edges + TILE - 1) / TILE;
    edge_update_mma<<<grid, THREADS, SMEM_BYTES>>>(
        edge_features, edge_src, edge_dst,
        b1, b2, gamma, beta, out, n_edges);
}